// round 1
// baseline (speedup 1.0000x reference)
#include <cuda_runtime.h>
#include <cstdint>

#define NP 1000000
#define KSEG 30
#define H 128

// ---------------- scratch (device globals; no allocation allowed) ----------
__device__ unsigned g_umax[KSEG * 3];
__device__ unsigned g_umin[KSEG * 3];
__device__ float    g_xc[KSEG * 3];
__device__ int      g_ind[NP];

// monotone float<->unsigned mapping (order-preserving)
__device__ __forceinline__ unsigned fenc(float f) {
    unsigned u = __float_as_uint(f);
    return (u & 0x80000000u) ? ~u : (u | 0x80000000u);
}
__device__ __forceinline__ float fdec(unsigned k) {
    unsigned u = (k & 0x80000000u) ? (k & 0x7FFFFFFFu) : ~k;
    return __uint_as_float(u);
}

// ---------------- kernel 0: reset reduction scratch (inside graph) ---------
__global__ void k_init() {
    int t = threadIdx.x;
    if (t < KSEG * 3) {
        g_umax[t] = 0u;           // encodes -inf-ish
        g_umin[t] = 0xFFFFFFFFu;  // encodes +inf-ish
    }
}

// ---------------- kernel 1: softmax+argmax, MLP, segment max/min -----------
// smem layout (floats): W2 16384 | W1 384 | b1 128 | b2 128 | W3 512 | b3 4
//                       | umax 90u | umin 90u
#define SMEM_FLOATS (16384 + 384 + 128 + 128 + 512 + 4)
#define SMEM_BYTES  (SMEM_FLOATS * 4 + (KSEG * 3) * 4 * 2)

__global__ void __launch_bounds__(128)
k_main(const float* __restrict__ pc1,
       const float* __restrict__ logits,
       const float* __restrict__ W1, const float* __restrict__ b1,
       const float* __restrict__ W2, const float* __restrict__ b2,
       const float* __restrict__ W3, const float* __restrict__ b3,
       float* __restrict__ out)
{
    extern __shared__ float sm[];
    float* W2s = sm;
    float* W1s = W2s + 16384;
    float* b1s = W1s + 384;
    float* b2s = b1s + 128;
    float* W3s = b2s + 128;
    float* b3s = W3s + 512;
    unsigned* umax = (unsigned*)(b3s + 4);
    unsigned* umin = umax + KSEG * 3;

    const int tid = threadIdx.x;

    for (int i = tid; i < 16384; i += 128) W2s[i] = W2[i];
    for (int i = tid; i < 384;   i += 128) W1s[i] = W1[i];
    if (tid < 128) { b1s[tid] = b1[tid]; b2s[tid] = b2[tid]; }
    for (int i = tid; i < 512;   i += 128) W3s[i] = W3[i];
    if (tid < 4) b3s[tid] = b3[tid];
    if (tid < KSEG * 3) { umax[tid] = 0u; umin[tid] = 0xFFFFFFFFu; }
    __syncthreads();

    float* outMask = out + (size_t)3  * NP;
    float* outT    = out + (size_t)33 * NP;
    float* outYaw  = out + (size_t)36 * NP;

    for (long long base = (long long)blockIdx.x * 128; base < NP;
         base += (long long)gridDim.x * 128)
    {
        int idx = (int)base + tid;
        if (idx < NP) {
            // ---- softmax over 30 logits + argmax (first max, like jnp.argmax)
            float lg[KSEG];
            const float* lrow = logits + (size_t)idx * KSEG;
            #pragma unroll
            for (int k = 0; k < KSEG; k++) lg[k] = lrow[k];

            int best = 0; float bm = lg[0];
            #pragma unroll
            for (int k = 1; k < KSEG; k++)
                if (lg[k] > bm) { bm = lg[k]; best = k; }

            float s = 0.f;
            #pragma unroll
            for (int k = 0; k < KSEG; k++) {
                float e = __expf(lg[k] - bm);
                lg[k] = e; s += e;
            }
            float inv = 1.0f / s;
            float* mrow = outMask + (size_t)idx * KSEG;
            #pragma unroll
            for (int k = 0; k < KSEG; k++) mrow[k] = lg[k] * inv;
            g_ind[idx] = best;

            // ---- segment max/min into smem (pre-reduction)
            float px = pc1[idx * 3 + 0];
            float py = pc1[idx * 3 + 1];
            float pz = pc1[idx * 3 + 2];
            atomicMax(&umax[best * 3 + 0], fenc(px));
            atomicMax(&umax[best * 3 + 1], fenc(py));
            atomicMax(&umax[best * 3 + 2], fenc(pz));
            atomicMin(&umin[best * 3 + 0], fenc(px));
            atomicMin(&umin[best * 3 + 1], fenc(py));
            atomicMin(&umin[best * 3 + 2], fenc(pz));

            // ---- MLP layer 1: h1 = relu(x*W1 + b1), kept in registers
            float h1r[H];
            #pragma unroll
            for (int i = 0; i < H; i++) {
                float a = fmaf(px, W1s[i],
                          fmaf(py, W1s[128 + i],
                          fmaf(pz, W1s[256 + i], b1s[i])));
                h1r[i] = fmaxf(a, 0.f);
            }

            // ---- layer 2 (broadcast W2 from smem) fused with layer 3
            float o0 = 0.f, o1 = 0.f, o2 = 0.f, o3 = 0.f;
            for (int j = 0; j < H; j++) {
                float a0 = 0.f, a1 = 0.f, a2 = 0.f, a3 = 0.f;
                #pragma unroll
                for (int i = 0; i < H; i += 4) {
                    a0 = fmaf(h1r[i + 0], W2s[(i + 0) * H + j], a0);
                    a1 = fmaf(h1r[i + 1], W2s[(i + 1) * H + j], a1);
                    a2 = fmaf(h1r[i + 2], W2s[(i + 2) * H + j], a2);
                    a3 = fmaf(h1r[i + 3], W2s[(i + 3) * H + j], a3);
                }
                float h2 = fmaxf(b2s[j] + ((a0 + a1) + (a2 + a3)), 0.f);
                o0 = fmaf(h2, W3s[j * 4 + 0], o0);
                o1 = fmaf(h2, W3s[j * 4 + 1], o1);
                o2 = fmaf(h2, W3s[j * 4 + 2], o2);
                o3 = fmaf(h2, W3s[j * 4 + 3], o3);
            }
            outT[idx * 3 + 0] = o0 + b3s[0];
            outT[idx * 3 + 1] = o1 + b3s[1];
            outT[idx * 3 + 2] = o2 + b3s[2];
            outYaw[idx]       = o3 + b3s[3];
        }
    }

    __syncthreads();
    if (tid < KSEG * 3) {
        atomicMax(&g_umax[tid], umax[tid]);
        atomicMin(&g_umin[tid], umin[tid]);
    }
}

// ---------------- kernel 2: cluster centers --------------------------------
__global__ void k_centers() {
    int t = threadIdx.x;
    if (t < KSEG * 3)
        g_xc[t] = 0.5f * (fdec(g_umax[t]) + fdec(g_umin[t]));
}

// ---------------- kernel 3: flow ------------------------------------------
__global__ void k_flow(const float* __restrict__ pc1, float* __restrict__ out)
{
    int idx = blockIdx.x * blockDim.x + threadIdx.x;
    if (idx >= NP) return;

    const float* outT   = out + (size_t)33 * NP;
    const float* outYaw = out + (size_t)36 * NP;

    int ind = g_ind[idx];
    float xcx = g_xc[ind * 3 + 0];
    float xcy = g_xc[ind * 3 + 1];
    float xcz = g_xc[ind * 3 + 2];

    float px = pc1[idx * 3 + 0];
    float py = pc1[idx * 3 + 1];
    float pz = pc1[idx * 3 + 2];

    float dx = px - xcx, dy = py - xcy, dz = pz - xcz;

    float yaw = outYaw[idx];
    float c, s;
    sincosf(yaw, &s, &c);

    float rx = c * dx - s * dy;
    float ry = s * dx + c * dy;
    float rz = dz;

    float tx = outT[idx * 3 + 0];
    float ty = outT[idx * 3 + 1];
    float tz = outT[idx * 3 + 2];

    // pred_flow = (rot + x_c + t) - p
    out[idx * 3 + 0] = (rx + xcx + tx) - px;
    out[idx * 3 + 1] = (ry + xcy + ty) - py;
    out[idx * 3 + 2] = (rz + xcz + tz) - pz;
}

// ---------------- launcher --------------------------------------------------
extern "C" void kernel_launch(void* const* d_in, const int* in_sizes, int n_in,
                              void* d_out, int out_size)
{
    const float* pc1    = (const float*)d_in[0];
    const float* logits = (const float*)d_in[1];
    const float* W1     = (const float*)d_in[2];
    const float* b1     = (const float*)d_in[3];
    const float* W2     = (const float*)d_in[4];
    const float* b2     = (const float*)d_in[5];
    const float* W3     = (const float*)d_in[6];
    const float* b3     = (const float*)d_in[7];
    float* out = (float*)d_out;

    cudaFuncSetAttribute(k_main, cudaFuncAttributeMaxDynamicSharedMemorySize,
                         SMEM_BYTES);

    k_init<<<1, 128>>>();
    k_main<<<456, 128, SMEM_BYTES>>>(pc1, logits, W1, b1, W2, b2, W3, b3, out);
    k_centers<<<1, 128>>>();
    k_flow<<<(NP + 255) / 256, 256>>>(pc1, out);
}

// round 2
// speedup vs baseline: 1.7874x; 1.7874x over previous
#include <cuda_runtime.h>
#include <cstdint>

#define NP 1000000
#define KSEG 30
#define H 128

typedef unsigned long long ull;

// ---------------- scratch (device globals; no allocation allowed) ----------
__device__ unsigned g_umax[KSEG * 3];
__device__ unsigned g_umin[KSEG * 3];
__device__ float    g_xc[KSEG * 3];
__device__ int      g_ind[NP];

// monotone float<->unsigned mapping (order-preserving)
__device__ __forceinline__ unsigned fenc(float f) {
    unsigned u = __float_as_uint(f);
    return (u & 0x80000000u) ? ~u : (u | 0x80000000u);
}
__device__ __forceinline__ float fdec(unsigned k) {
    unsigned u = (k & 0x80000000u) ? (k & 0x7FFFFFFFu) : ~k;
    return __uint_as_float(u);
}

// ---------------- packed f32x2 helpers (Blackwell 2x fp32 path) ------------
__device__ __forceinline__ ull pack2(float lo, float hi) {
    ull r; asm("mov.b64 %0, {%1, %2};" : "=l"(r) : "f"(lo), "f"(hi)); return r;
}
__device__ __forceinline__ ull ffma2(ull a, ull b, ull c) {
    ull d; asm("fma.rn.f32x2 %0, %1, %2, %3;" : "=l"(d) : "l"(a), "l"(b), "l"(c));
    return d;
}
__device__ __forceinline__ ull fadd2(ull a, ull b) {
    ull d; asm("add.rn.f32x2 %0, %1, %2;" : "=l"(d) : "l"(a), "l"(b));
    return d;
}
__device__ __forceinline__ void unpack2(ull v, float& lo, float& hi) {
    asm("mov.b64 {%0, %1}, %2;" : "=f"(lo), "=f"(hi) : "l"(v));
}

// ---------------- kernel 0: reset reduction scratch (inside graph) ---------
__global__ void k_init() {
    int t = threadIdx.x;
    if (t < KSEG * 3) {
        g_umax[t] = 0u;           // encodes -inf-ish
        g_umin[t] = 0xFFFFFFFFu;  // encodes +inf-ish
    }
}

// ---------------- kernel 1: softmax+argmax, MLP, segment max/min -----------
// smem layout (floats): W2t 16384 (TRANSPOSED, [j][i]) | W1 384 | b1 128
//                       | b2 128 | W3 512 | b3 4 | umax 90u | umin 90u
#define SMEM_FLOATS (16384 + 384 + 128 + 128 + 512 + 4)
#define SMEM_BYTES  (SMEM_FLOATS * 4 + (KSEG * 3) * 4 * 2)

__global__ void __launch_bounds__(128, 3)
k_main(const float* __restrict__ pc1,
       const float* __restrict__ logits,
       const float* __restrict__ W1, const float* __restrict__ b1,
       const float* __restrict__ W2, const float* __restrict__ b2,
       const float* __restrict__ W3, const float* __restrict__ b3,
       float* __restrict__ out)
{
    extern __shared__ float sm[];
    float* W2s = sm;                 // transposed: W2s[j*H + i] = W2[i*H + j]
    float* W1s = W2s + 16384;
    float* b1s = W1s + 384;
    float* b2s = b1s + 128;
    float* W3s = b2s + 128;
    float* b3s = W3s + 512;
    unsigned* umax = (unsigned*)(b3s + 4);
    unsigned* umin = umax + KSEG * 3;

    const int tid = threadIdx.x;

    // transpose W2 into smem (coalesced reads; one-time STS conflicts are fine)
    for (int x = tid; x < H * H; x += 128) {
        int i = x >> 7, j = x & 127;
        W2s[j * H + i] = W2[x];
    }
    for (int i = tid; i < 384; i += 128) W1s[i] = W1[i];
    if (tid < 128) { b1s[tid] = b1[tid]; b2s[tid] = b2[tid]; }
    for (int i = tid; i < 512; i += 128) W3s[i] = W3[i];
    if (tid < 4) b3s[tid] = b3[tid];
    if (tid < KSEG * 3) { umax[tid] = 0u; umin[tid] = 0xFFFFFFFFu; }
    __syncthreads();

    float* outMask = out + (size_t)3  * NP;
    float* outT    = out + (size_t)33 * NP;
    float* outYaw  = out + (size_t)36 * NP;

    for (long long base = (long long)blockIdx.x * 128; base < NP;
         base += (long long)gridDim.x * 128)
    {
        int idx = (int)base + tid;
        if (idx < NP) {
            // ---- softmax over 30 logits + argmax (first max, like jnp.argmax)
            float lg[KSEG];
            const float* lrow = logits + (size_t)idx * KSEG;
            #pragma unroll
            for (int k = 0; k < KSEG; k++) lg[k] = lrow[k];

            int best = 0; float bm = lg[0];
            #pragma unroll
            for (int k = 1; k < KSEG; k++)
                if (lg[k] > bm) { bm = lg[k]; best = k; }

            float s = 0.f;
            #pragma unroll
            for (int k = 0; k < KSEG; k++) {
                float e = __expf(lg[k] - bm);
                lg[k] = e; s += e;
            }
            float inv = 1.0f / s;
            float* mrow = outMask + (size_t)idx * KSEG;
            #pragma unroll
            for (int k = 0; k < KSEG; k++) mrow[k] = lg[k] * inv;
            g_ind[idx] = best;

            // ---- segment max/min into smem (pre-reduction)
            float px = pc1[idx * 3 + 0];
            float py = pc1[idx * 3 + 1];
            float pz = pc1[idx * 3 + 2];
            atomicMax(&umax[best * 3 + 0], fenc(px));
            atomicMax(&umax[best * 3 + 1], fenc(py));
            atomicMax(&umax[best * 3 + 2], fenc(pz));
            atomicMin(&umin[best * 3 + 0], fenc(px));
            atomicMin(&umin[best * 3 + 1], fenc(py));
            atomicMin(&umin[best * 3 + 2], fenc(pz));

            // ---- MLP layer 1: h1 = relu(x*W1 + b1), packed as 64 f32x2 regs
            ull h1p[H / 2];
            #pragma unroll
            for (int m = 0; m < H / 2; m++) {
                int i0 = 2 * m, i1 = 2 * m + 1;
                float v0 = fmaf(px, W1s[i0],
                           fmaf(py, W1s[128 + i0],
                           fmaf(pz, W1s[256 + i0], b1s[i0])));
                float v1 = fmaf(px, W1s[i1],
                           fmaf(py, W1s[128 + i1],
                           fmaf(pz, W1s[256 + i1], b1s[i1])));
                h1p[m] = pack2(fmaxf(v0, 0.f), fmaxf(v1, 0.f));
            }

            // ---- layer 2 (broadcast LDS.128 of transposed W2 + FFMA2)
            //      fused with layer 3 (packed pairs from W3 rows)
            ull o01 = 0ULL, o23 = 0ULL;
            const ulonglong2* w3p = (const ulonglong2*)W3s;
            for (int j = 0; j < H; j++) {
                const ulonglong2* w2row =
                    (const ulonglong2*)(W2s + j * H);   // 32 x 16B, broadcast
                ull a0 = 0ULL, a1 = 0ULL, a2 = 0ULL, a3 = 0ULL;
                #pragma unroll
                for (int m = 0; m < 32; m += 2) {
                    ulonglong2 w0 = w2row[m];
                    ulonglong2 w1 = w2row[m + 1];
                    a0 = ffma2(h1p[2 * m + 0], w0.x, a0);
                    a1 = ffma2(h1p[2 * m + 1], w0.y, a1);
                    a2 = ffma2(h1p[2 * m + 2], w1.x, a2);
                    a3 = ffma2(h1p[2 * m + 3], w1.y, a3);
                }
                ull sacc = fadd2(fadd2(a0, a1), fadd2(a2, a3));
                float slo, shi; unpack2(sacc, slo, shi);
                float h2 = fmaxf(b2s[j] + (slo + shi), 0.f);

                ulonglong2 w3 = w3p[j];                 // (W3[j][0..1], W3[j][2..3])
                ull h2x2 = pack2(h2, h2);
                o01 = ffma2(h2x2, w3.x, o01);
                o23 = ffma2(h2x2, w3.y, o23);
            }
            float o0, o1, o2, o3;
            unpack2(o01, o0, o1);
            unpack2(o23, o2, o3);
            outT[idx * 3 + 0] = o0 + b3s[0];
            outT[idx * 3 + 1] = o1 + b3s[1];
            outT[idx * 3 + 2] = o2 + b3s[2];
            outYaw[idx]       = o3 + b3s[3];
        }
    }

    __syncthreads();
    if (tid < KSEG * 3) {
        atomicMax(&g_umax[tid], umax[tid]);
        atomicMin(&g_umin[tid], umin[tid]);
    }
}

// ---------------- kernel 2: cluster centers --------------------------------
__global__ void k_centers() {
    int t = threadIdx.x;
    if (t < KSEG * 3)
        g_xc[t] = 0.5f * (fdec(g_umax[t]) + fdec(g_umin[t]));
}

// ---------------- kernel 3: flow ------------------------------------------
__global__ void k_flow(const float* __restrict__ pc1, float* __restrict__ out)
{
    int idx = blockIdx.x * blockDim.x + threadIdx.x;
    if (idx >= NP) return;

    const float* outT   = out + (size_t)33 * NP;
    const float* outYaw = out + (size_t)36 * NP;

    int ind = g_ind[idx];
    float xcx = g_xc[ind * 3 + 0];
    float xcy = g_xc[ind * 3 + 1];
    float xcz = g_xc[ind * 3 + 2];

    float px = pc1[idx * 3 + 0];
    float py = pc1[idx * 3 + 1];
    float pz = pc1[idx * 3 + 2];

    float dx = px - xcx, dy = py - xcy, dz = pz - xcz;

    float yaw = outYaw[idx];
    float c, s;
    sincosf(yaw, &s, &c);

    float rx = c * dx - s * dy;
    float ry = s * dx + c * dy;
    float rz = dz;

    float tx = outT[idx * 3 + 0];
    float ty = outT[idx * 3 + 1];
    float tz = outT[idx * 3 + 2];

    // pred_flow = (rot + x_c + t) - p
    out[idx * 3 + 0] = (rx + xcx + tx) - px;
    out[idx * 3 + 1] = (ry + xcy + ty) - py;
    out[idx * 3 + 2] = (rz + xcz + tz) - pz;
}

// ---------------- launcher --------------------------------------------------
extern "C" void kernel_launch(void* const* d_in, const int* in_sizes, int n_in,
                              void* d_out, int out_size)
{
    const float* pc1    = (const float*)d_in[0];
    const float* logits = (const float*)d_in[1];
    const float* W1     = (const float*)d_in[2];
    const float* b1     = (const float*)d_in[3];
    const float* W2     = (const float*)d_in[4];
    const float* b2     = (const float*)d_in[5];
    const float* W3     = (const float*)d_in[6];
    const float* b3     = (const float*)d_in[7];
    float* out = (float*)d_out;

    cudaFuncSetAttribute(k_main, cudaFuncAttributeMaxDynamicSharedMemorySize,
                         SMEM_BYTES);

    k_init<<<1, 128>>>();
    k_main<<<456, 128, SMEM_BYTES>>>(pc1, logits, W1, b1, W2, b2, W3, b3, out);
    k_centers<<<1, 128>>>();
    k_flow<<<(NP + 255) / 256, 256>>>(pc1, out);
}

// round 4
// speedup vs baseline: 4.4575x; 2.4939x over previous
#include <cuda_runtime.h>
#include <cuda_bf16.h>
#include <cstdint>

#define NP   1000000
#define KSEG 30
#define H    128

#define WTILES (NP / 16)      // 62500 warp-tiles of 16 points
#define GRID_MMA 304
#define WARPS_PER_BLK 8

typedef unsigned int uint;

// ---------------- scratch (device globals; no allocation allowed) ----------
__device__ unsigned g_umax[KSEG * 3];
__device__ unsigned g_umin[KSEG * 3];
__device__ float    g_xc[KSEG * 3];
__device__ int      g_ind[NP];

__device__ __forceinline__ unsigned fenc(float f) {
    unsigned u = __float_as_uint(f);
    return (u & 0x80000000u) ? ~u : (u | 0x80000000u);
}
__device__ __forceinline__ float fdec(unsigned k) {
    unsigned u = (k & 0x80000000u) ? (k & 0x7FFFFFFFu) : ~k;
    return __uint_as_float(u);
}

// ---------------- small PTX helpers (all baseline features) ----------------
__device__ __forceinline__ uint smem_u32(const void* p) {
    uint a;
    asm("{ .reg .u64 t; cvta.to.shared.u64 t, %1; cvt.u32.u64 %0, t; }"
        : "=r"(a) : "l"(p));
    return a;
}
// pack two fp32 into bf16x2: reg.lo = c0, reg.hi = c1
__device__ __forceinline__ uint pack_bf16x2(float c0, float c1) {
    uint r;
    asm("cvt.rn.bf16x2.f32 %0, %1, %2;" : "=r"(r) : "f"(c1), "f"(c0));
    return r;
}
__device__ __forceinline__ float bf16_round(float v) {
    return __bfloat162float(__float2bfloat16_rn(v));
}
__device__ __forceinline__ void ldsm_x2_t(uint& r0, uint& r1, uint addr) {
    asm volatile("ldmatrix.sync.aligned.m8n8.x2.trans.shared.b16 {%0,%1}, [%2];"
                 : "=r"(r0), "=r"(r1) : "r"(addr));
}
__device__ __forceinline__ void mma16816(float& d0, float& d1, float& d2, float& d3,
                                         uint a0, uint a1, uint a2, uint a3,
                                         uint b0, uint b1) {
    asm volatile("mma.sync.aligned.m16n8k16.row.col.f32.bf16.bf16.f32 "
                 "{%0,%1,%2,%3}, {%4,%5,%6,%7}, {%8,%9}, {%0,%1,%2,%3};"
                 : "+f"(d0), "+f"(d1), "+f"(d2), "+f"(d3)
                 : "r"(a0), "r"(a1), "r"(a2), "r"(a3), "r"(b0), "r"(b1));
}

// ---------------- kernel 0: reset reduction scratch ------------------------
__global__ void k_init() {
    int t = threadIdx.x;
    if (t < KSEG * 3) { g_umax[t] = 0u; g_umin[t] = 0xFFFFFFFFu; }
}

// ---------------- kernel 1: softmax + argmax + segment max/min -------------
__global__ void __launch_bounds__(256)
k_soft(const float* __restrict__ pc1, const float* __restrict__ logits,
       float* __restrict__ out)
{
    __shared__ unsigned umax[KSEG * 3];
    __shared__ unsigned umin[KSEG * 3];
    int tid = threadIdx.x;
    if (tid < KSEG * 3) { umax[tid] = 0u; umin[tid] = 0xFFFFFFFFu; }
    __syncthreads();

    float* outMask = out + (size_t)3 * NP;
    int idx = blockIdx.x * 256 + tid;
    if (idx < NP) {
        float lg[KSEG];
        const float* lrow = logits + (size_t)idx * KSEG;
        #pragma unroll
        for (int k = 0; k < KSEG; k++) lg[k] = lrow[k];

        int best = 0; float bm = lg[0];
        #pragma unroll
        for (int k = 1; k < KSEG; k++)
            if (lg[k] > bm) { bm = lg[k]; best = k; }

        float s = 0.f;
        #pragma unroll
        for (int k = 0; k < KSEG; k++) { float e = __expf(lg[k] - bm); lg[k] = e; s += e; }
        float inv = 1.0f / s;
        float* mrow = outMask + (size_t)idx * KSEG;
        #pragma unroll
        for (int k = 0; k < KSEG; k++) mrow[k] = lg[k] * inv;
        g_ind[idx] = best;

        float px = pc1[idx * 3 + 0];
        float py = pc1[idx * 3 + 1];
        float pz = pc1[idx * 3 + 2];
        atomicMax(&umax[best * 3 + 0], fenc(px));
        atomicMax(&umax[best * 3 + 1], fenc(py));
        atomicMax(&umax[best * 3 + 2], fenc(pz));
        atomicMin(&umin[best * 3 + 0], fenc(px));
        atomicMin(&umin[best * 3 + 1], fenc(py));
        atomicMin(&umin[best * 3 + 2], fenc(pz));
    }
    __syncthreads();
    if (tid < KSEG * 3) {
        atomicMax(&g_umax[tid], umax[tid]);
        atomicMin(&g_umin[tid], umin[tid]);
    }
}

// ---------------- kernel 2: cluster centers --------------------------------
__global__ void k_centers() {
    int t = threadIdx.x;
    if (t < KSEG * 3) g_xc[t] = 0.5f * (fdec(g_umax[t]) + fdec(g_umin[t]));
}

// ---------------- kernel 3: MLP via mma.sync bf16 (split hi/lo, 3 terms) ---
// smem byte layout:
//   [0)       Bhi : 128 x 136 bf16   (34816 B)  row stride 136 elems (272 B)
//   [34816)   Blo : 128 x 136 bf16   (34816 B)
//   [69632)   W1s : 384 f32          (1536 B)
//   [71168)   b1s : 128 f32          (512 B)
//   [71680)   b2s : 128 f32          (512 B)
//   [72192)   W3s : 512 f32          (2048 B)
//   [74240)   b3s : 4 f32            (16 B)
#define OFF_BHI 0
#define OFF_BLO 34816
#define OFF_W1  69632
#define OFF_B1  71168
#define OFF_B2  71680
#define OFF_W3  72192
#define OFF_B3  74240
#define SM_TOTAL 74256
#define LDB 136   // bf16 elems per B row

__global__ void __launch_bounds__(256, 2)
k_mma(const float* __restrict__ pc1,
      const float* __restrict__ W1, const float* __restrict__ b1,
      const float* __restrict__ W2, const float* __restrict__ b2,
      const float* __restrict__ W3, const float* __restrict__ b3,
      float* __restrict__ out)
{
    extern __shared__ char smc[];
    __nv_bfloat16* BhiS = (__nv_bfloat16*)(smc + OFF_BHI);
    __nv_bfloat16* BloS = (__nv_bfloat16*)(smc + OFF_BLO);
    float* W1s = (float*)(smc + OFF_W1);
    float* b1s = (float*)(smc + OFF_B1);
    float* b2s = (float*)(smc + OFF_B2);
    float* W3s = (float*)(smc + OFF_W3);
    float* b3s = (float*)(smc + OFF_B3);

    const int tid = threadIdx.x;

    // one-time weight load + bf16 split of W2 (B operand, [k=i][n=j])
    for (int x = tid; x < H * H; x += 256) {
        int i = x >> 7, j = x & 127;
        float v  = W2[x];
        float hi = bf16_round(v);
        BhiS[i * LDB + j] = __float2bfloat16_rn(hi);
        BloS[i * LDB + j] = __float2bfloat16_rn(v - hi);
    }
    for (int i = tid; i < 384; i += 256) W1s[i] = W1[i];
    if (tid < 128) { b1s[tid] = b1[tid]; b2s[tid] = b2[tid]; }
    for (int i = tid; i < 512; i += 256) W3s[i] = W3[i];
    if (tid < 4) b3s[tid] = b3[tid];
    __syncthreads();

    const int w  = tid >> 5;
    const int l  = tid & 31;
    const int lq = l & 3;     // quad id -> j columns
    const int lr = l >> 2;    // row group -> point rows

    // ldmatrix row base for this lane (lanes 0..15 used; 16..31 mirror)
    const uint bhi_base = smem_u32(BhiS) + (uint)(l & 15) * (LDB * 2);
    const uint blo_base = smem_u32(BloS) + (uint)(l & 15) * (LDB * 2);

    float* outT   = out + (size_t)33 * NP;
    float* outYaw = out + (size_t)36 * NP;

    for (int wt = blockIdx.x * WARPS_PER_BLK + w; wt < WTILES;
         wt += GRID_MMA * WARPS_PER_BLK)
    {
        const int base = wt * 16;
        const int p0 = base + lr;
        const int p1 = p0 + 8;
        float x0 = pc1[p0 * 3 + 0], y0 = pc1[p0 * 3 + 1], z0 = pc1[p0 * 3 + 2];
        float x1 = pc1[p1 * 3 + 0], y1 = pc1[p1 * 3 + 1], z1 = pc1[p1 * 3 + 2];

        // ---- layer 1 directly into A fragments (hi/lo bf16 split)
        uint ahi[8][4], alo[8][4];
        #pragma unroll
        for (int kk = 0; kk < 8; kk++) {
            int ib = kk * 16 + lq * 2;
            float v0[4], v1[4];
            #pragma unroll
            for (int u = 0; u < 4; u++) {
                int i = ib + ((u >> 1) * 8) + (u & 1);   // {0,1,8,9}
                float w1x = W1s[i], w1y = W1s[128 + i], w1z = W1s[256 + i];
                float bb  = b1s[i];
                v0[u] = fmaxf(fmaf(x0, w1x, fmaf(y0, w1y, fmaf(z0, w1z, bb))), 0.f);
                v1[u] = fmaxf(fmaf(x1, w1x, fmaf(y1, w1y, fmaf(z1, w1z, bb))), 0.f);
            }
            // a0=(r,c0c1) a1=(r+8,c0c1) a2=(r,c8c9) a3=(r+8,c8c9)
            float h00 = bf16_round(v0[0]), h01 = bf16_round(v0[1]);
            float h02 = bf16_round(v0[2]), h03 = bf16_round(v0[3]);
            float h10 = bf16_round(v1[0]), h11 = bf16_round(v1[1]);
            float h12 = bf16_round(v1[2]), h13 = bf16_round(v1[3]);
            ahi[kk][0] = pack_bf16x2(h00, h01);
            ahi[kk][1] = pack_bf16x2(h10, h11);
            ahi[kk][2] = pack_bf16x2(h02, h03);
            ahi[kk][3] = pack_bf16x2(h12, h13);
            alo[kk][0] = pack_bf16x2(v0[0] - h00, v0[1] - h01);
            alo[kk][1] = pack_bf16x2(v1[0] - h10, v1[1] - h11);
            alo[kk][2] = pack_bf16x2(v0[2] - h02, v0[3] - h03);
            alo[kk][3] = pack_bf16x2(v1[2] - h12, v1[3] - h13);
        }

        // ---- GEMM over 16 n-chunks of 8 columns, fused epilogue
        float oA0 = 0.f, oA1 = 0.f, oA2 = 0.f, oA3 = 0.f;   // point p0
        float oB0 = 0.f, oB1 = 0.f, oB2 = 0.f, oB3 = 0.f;   // point p1
        for (int n = 0; n < 16; n++) {
            float d00=0.f,d01=0.f,d02=0.f,d03=0.f;   // Ahi*Bhi
            float d10=0.f,d11=0.f,d12=0.f,d13=0.f;   // Ahi*Blo
            float d20=0.f,d21=0.f,d22=0.f,d23=0.f;   // Alo*Bhi
            uint ah = bhi_base + (uint)n * 16u;
            uint al = blo_base + (uint)n * 16u;
            #pragma unroll
            for (int kk = 0; kk < 8; kk++) {
                uint bh0, bh1, bl0, bl1;
                ldsm_x2_t(bh0, bh1, ah + (uint)kk * (16u * LDB * 2));
                ldsm_x2_t(bl0, bl1, al + (uint)kk * (16u * LDB * 2));
                mma16816(d00,d01,d02,d03,
                         ahi[kk][0],ahi[kk][1],ahi[kk][2],ahi[kk][3], bh0,bh1);
                mma16816(d10,d11,d12,d13,
                         ahi[kk][0],ahi[kk][1],ahi[kk][2],ahi[kk][3], bl0,bl1);
                mma16816(d20,d21,d22,d23,
                         alo[kk][0],alo[kk][1],alo[kk][2],alo[kk][3], bh0,bh1);
            }
            int j0 = n * 8 + lq * 2;
            float2 b2p = *(const float2*)&b2s[j0];
            // D layout: d0=(r,j0) d1=(r,j1) d2=(r+8,j0) d3=(r+8,j1)
            float hA0 = fmaxf(d00 + d10 + d20 + b2p.x, 0.f);
            float hA1 = fmaxf(d01 + d11 + d21 + b2p.y, 0.f);
            float hB0 = fmaxf(d02 + d12 + d22 + b2p.x, 0.f);
            float hB1 = fmaxf(d03 + d13 + d23 + b2p.y, 0.f);
            float4 wA = *(const float4*)&W3s[j0 * 4];
            float4 wB = *(const float4*)&W3s[j0 * 4 + 4];
            oA0 = fmaf(hA0, wA.x, fmaf(hA1, wB.x, oA0));
            oA1 = fmaf(hA0, wA.y, fmaf(hA1, wB.y, oA1));
            oA2 = fmaf(hA0, wA.z, fmaf(hA1, wB.z, oA2));
            oA3 = fmaf(hA0, wA.w, fmaf(hA1, wB.w, oA3));
            oB0 = fmaf(hB0, wA.x, fmaf(hB1, wB.x, oB0));
            oB1 = fmaf(hB0, wA.y, fmaf(hB1, wB.y, oB1));
            oB2 = fmaf(hB0, wA.z, fmaf(hB1, wB.z, oB2));
            oB3 = fmaf(hB0, wA.w, fmaf(hB1, wB.w, oB3));
        }

        // ---- reduce partial o across the 4 lanes of each quad (lq = bits 0,1)
        #pragma unroll
        for (int off = 1; off <= 2; off <<= 1) {
            oA0 += __shfl_xor_sync(0xFFFFFFFFu, oA0, off);
            oA1 += __shfl_xor_sync(0xFFFFFFFFu, oA1, off);
            oA2 += __shfl_xor_sync(0xFFFFFFFFu, oA2, off);
            oA3 += __shfl_xor_sync(0xFFFFFFFFu, oA3, off);
            oB0 += __shfl_xor_sync(0xFFFFFFFFu, oB0, off);
            oB1 += __shfl_xor_sync(0xFFFFFFFFu, oB1, off);
            oB2 += __shfl_xor_sync(0xFFFFFFFFu, oB2, off);
            oB3 += __shfl_xor_sync(0xFFFFFFFFu, oB3, off);
        }
        if (lq == 0) {
            outT[p0 * 3 + 0] = oA0 + b3s[0];
            outT[p0 * 3 + 1] = oA1 + b3s[1];
            outT[p0 * 3 + 2] = oA2 + b3s[2];
            outYaw[p0]       = oA3 + b3s[3];
            outT[p1 * 3 + 0] = oB0 + b3s[0];
            outT[p1 * 3 + 1] = oB1 + b3s[1];
            outT[p1 * 3 + 2] = oB2 + b3s[2];
            outYaw[p1]       = oB3 + b3s[3];
        }
    }
}

// ---------------- kernel 4: flow -------------------------------------------
__global__ void k_flow(const float* __restrict__ pc1, float* __restrict__ out)
{
    int idx = blockIdx.x * blockDim.x + threadIdx.x;
    if (idx >= NP) return;

    const float* outT   = out + (size_t)33 * NP;
    const float* outYaw = out + (size_t)36 * NP;

    int ind = g_ind[idx];
    float xcx = g_xc[ind*3+0], xcy = g_xc[ind*3+1], xcz = g_xc[ind*3+2];
    float px = pc1[idx*3+0], py = pc1[idx*3+1], pz = pc1[idx*3+2];
    float dx = px - xcx, dy = py - xcy, dz = pz - xcz;

    float yaw = outYaw[idx];
    float c, s; sincosf(yaw, &s, &c);

    float rx = c*dx - s*dy;
    float ry = s*dx + c*dy;

    float tx = outT[idx*3+0], ty = outT[idx*3+1], tz = outT[idx*3+2];

    out[idx*3+0] = (rx + xcx + tx) - px;
    out[idx*3+1] = (ry + xcy + ty) - py;
    out[idx*3+2] = (dz + xcz + tz) - pz;
}

// ---------------- launcher --------------------------------------------------
extern "C" void kernel_launch(void* const* d_in, const int* in_sizes, int n_in,
                              void* d_out, int out_size)
{
    const float* pc1    = (const float*)d_in[0];
    const float* logits = (const float*)d_in[1];
    const float* W1     = (const float*)d_in[2];
    const float* b1     = (const float*)d_in[3];
    const float* W2     = (const float*)d_in[4];
    const float* b2     = (const float*)d_in[5];
    const float* W3     = (const float*)d_in[6];
    const float* b3     = (const float*)d_in[7];
    float* out = (float*)d_out;

    cudaFuncSetAttribute(k_mma, cudaFuncAttributeMaxDynamicSharedMemorySize,
                         SM_TOTAL);

    k_init<<<1, 128>>>();
    k_soft<<<(NP + 255) / 256, 256>>>(pc1, logits, out);
    k_centers<<<1, 128>>>();
    k_mma<<<GRID_MMA, 256, SM_TOTAL>>>(pc1, W1, b1, W2, b2, W3, b3, out);
    k_flow<<<(NP + 255) / 256, 256>>>(pc1, out);
}

// round 5
// speedup vs baseline: 6.0860x; 1.3654x over previous
#include <cuda_runtime.h>
#include <cuda_bf16.h>
#include <cstdint>

#define NP   1000000
#define KSEG 30
#define H    128

#define WTILES (NP / 16)      // 62500 warp-tiles of 16 points
#define GRID_MMA 304
#define WARPS_PER_BLK 8

typedef unsigned int uint;

// ---------------- scratch (device globals; no allocation allowed) ----------
__device__ unsigned g_umax[KSEG * 3];
__device__ unsigned g_umin[KSEG * 3];
__device__ float    g_xc[KSEG * 3];
__device__ int      g_ind[NP];

__device__ __forceinline__ unsigned fenc(float f) {
    unsigned u = __float_as_uint(f);
    return (u & 0x80000000u) ? ~u : (u | 0x80000000u);
}
__device__ __forceinline__ float fdec(unsigned k) {
    unsigned u = (k & 0x80000000u) ? (k & 0x7FFFFFFFu) : ~k;
    return __uint_as_float(u);
}

// ---------------- small PTX helpers (all baseline features) ----------------
__device__ __forceinline__ uint smem_u32(const void* p) {
    uint a;
    asm("{ .reg .u64 t; cvta.to.shared.u64 t, %1; cvt.u32.u64 %0, t; }"
        : "=r"(a) : "l"(p));
    return a;
}
// pack two fp32 into bf16x2: reg.lo = c0, reg.hi = c1
__device__ __forceinline__ uint pack_bf16x2(float c0, float c1) {
    uint r;
    asm("cvt.rn.bf16x2.f32 %0, %1, %2;" : "=r"(r) : "f"(c1), "f"(c0));
    return r;
}
__device__ __forceinline__ float bf16_round(float v) {
    return __bfloat162float(__float2bfloat16_rn(v));
}
// x4 trans ldmatrix: lanes 0-15 give Bhi row addrs, lanes 16-31 Blo row addrs
// -> r0,r1 = Bhi k0-7,k8-15 ; r2,r3 = Blo k0-7,k8-15
__device__ __forceinline__ void ldsm_x4_t(uint& r0, uint& r1, uint& r2, uint& r3,
                                          uint addr) {
    asm volatile("ldmatrix.sync.aligned.m8n8.x4.trans.shared.b16 {%0,%1,%2,%3}, [%4];"
                 : "=r"(r0), "=r"(r1), "=r"(r2), "=r"(r3) : "r"(addr));
}
__device__ __forceinline__ void mma16816(float& d0, float& d1, float& d2, float& d3,
                                         uint a0, uint a1, uint a2, uint a3,
                                         uint b0, uint b1) {
    asm volatile("mma.sync.aligned.m16n8k16.row.col.f32.bf16.bf16.f32 "
                 "{%0,%1,%2,%3}, {%4,%5,%6,%7}, {%8,%9}, {%0,%1,%2,%3};"
                 : "+f"(d0), "+f"(d1), "+f"(d2), "+f"(d3)
                 : "r"(a0), "r"(a1), "r"(a2), "r"(a3), "r"(b0), "r"(b1));
}

// ---------------- kernel 0: reset reduction scratch ------------------------
__global__ void k_init() {
    int t = threadIdx.x;
    if (t < KSEG * 3) { g_umax[t] = 0u; g_umin[t] = 0xFFFFFFFFu; }
}

// ---------------- kernel 1: cluster centers (after fused kernel) -----------
__global__ void k_centers() {
    int t = threadIdx.x;
    if (t < KSEG * 3) g_xc[t] = 0.5f * (fdec(g_umax[t]) + fdec(g_umin[t]));
}

// ---------------- fused kernel: softmax+argmax+segmax + MLP (mma.sync) -----
// smem byte layout:
//   [0)      Bhi : 128 x 136 bf16  (34816)  row stride 272 B
//   [34816)  Blo : 128 x 136 bf16  (34816)
//   [69632)  W14 : 128 float4 (w1x,w1y,w1z,b1)   (2048)
//   [71680)  b2s : 128 f32   (512)
//   [72192)  W3s : 512 f32   (2048)
//   [74240)  b3s : 4 f32     (16)
//   [74256)  umax: 90 u32    (360)
//   [74616)  umin: 90 u32    (360)
//   [74976)  buf : 8 warps x 496 f32  (15872)   (480 logits + 16 sinv)
#define OFF_BHI 0
#define OFF_BLO 34816
#define OFF_W14 69632
#define OFF_B2  71680
#define OFF_W3  72192
#define OFF_B3  74240
#define OFF_UMX 74256
#define OFF_UMN 74616
#define OFF_BUF 74976
#define SM_TOTAL 90848
#define LDB 136   // bf16 elems per B row

__global__ void __launch_bounds__(256, 2)
k_fused(const float* __restrict__ pc1, const float* __restrict__ logits,
        const float* __restrict__ W1, const float* __restrict__ b1,
        const float* __restrict__ W2, const float* __restrict__ b2,
        const float* __restrict__ W3, const float* __restrict__ b3,
        float* __restrict__ out)
{
    extern __shared__ char smc[];
    __nv_bfloat16* BhiS = (__nv_bfloat16*)(smc + OFF_BHI);
    __nv_bfloat16* BloS = (__nv_bfloat16*)(smc + OFF_BLO);
    float4*   W14 = (float4*)(smc + OFF_W14);
    float*    b2s = (float*)(smc + OFF_B2);
    float*    W3s = (float*)(smc + OFF_W3);
    float*    b3s = (float*)(smc + OFF_B3);
    unsigned* umax = (unsigned*)(smc + OFF_UMX);
    unsigned* umin = (unsigned*)(smc + OFF_UMN);

    const int tid = threadIdx.x;

    // one-time weight staging
    for (int x = tid; x < H * H; x += 256) {
        int i = x >> 7, j = x & 127;
        float v  = W2[x];
        float hi = bf16_round(v);
        BhiS[i * LDB + j] = __float2bfloat16_rn(hi);
        BloS[i * LDB + j] = __float2bfloat16_rn(v - hi);
    }
    if (tid < 128) {
        W14[tid] = make_float4(W1[tid], W1[128 + tid], W1[256 + tid], b1[tid]);
        b2s[tid] = b2[tid];
    }
    for (int i = tid; i < 512; i += 256) W3s[i] = W3[i];
    if (tid < 4) b3s[tid] = b3[tid];
    if (tid < KSEG * 3) { umax[tid] = 0u; umin[tid] = 0xFFFFFFFFu; }
    __syncthreads();

    const int w  = tid >> 5;
    const int l  = tid & 31;
    const int lq = l & 3;     // quad id -> j columns
    const int lr = l >> 2;    // row group -> point rows

    float* wbuf = (float*)(smc + OFF_BUF) + w * 496;
    float* sinv = wbuf + 480;

    // ldmatrix lane base: lanes 0-15 -> Bhi rows, lanes 16-31 -> Blo rows
    const uint bbase = smem_u32(BhiS) + (uint)(l & 15) * (LDB * 2)
                     + ((l & 16) ? (uint)(OFF_BLO - OFF_BHI) : 0u);

    float* outMask = out + (size_t)3  * NP;
    float* outT    = out + (size_t)33 * NP;
    float* outYaw  = out + (size_t)36 * NP;

    for (int wt = blockIdx.x * WARPS_PER_BLK + w; wt < WTILES;
         wt += GRID_MMA * WARPS_PER_BLK)
    {
        const int base = wt * 16;

        // ================= softmax + argmax + segment atomics ==============
        __syncwarp();   // protect wbuf/sinv reuse across iterations
        const float* lsrc = logits + (size_t)base * 30;
        #pragma unroll
        for (int r = 0; r < 15; r++) wbuf[r * 32 + l] = lsrc[r * 32 + l];
        __syncwarp();

        {
            int pl = l & 15, hf = l >> 4;
            float* my = wbuf + pl * 30 + hf * 15;
            float bv = my[0]; int bi = 0;
            #pragma unroll
            for (int k = 1; k < 15; k++) {
                float v = my[k];
                if (v > bv) { bv = v; bi = k; }
            }
            bi += hf * 15;
            float bvo = __shfl_xor_sync(0xFFFFFFFFu, bv, 16);
            int   bio = __shfl_xor_sync(0xFFFFFFFFu, bi, 16);
            if (bvo > bv || (bvo == bv && bio < bi)) { bv = bvo; bi = bio; }

            float acc = 0.f;
            #pragma unroll
            for (int k = 0; k < 15; k++) {
                float e = __expf(my[k] - bv);
                my[k] = e; acc += e;
            }
            acc += __shfl_xor_sync(0xFFFFFFFFu, acc, 16);

            if (hf == 0) {
                sinv[pl] = 1.0f / acc;
                int p = base + pl;
                g_ind[p] = bi;
                float qx = pc1[p * 3 + 0];
                float qy = pc1[p * 3 + 1];
                float qz = pc1[p * 3 + 2];
                atomicMax(&umax[bi * 3 + 0], fenc(qx));
                atomicMax(&umax[bi * 3 + 1], fenc(qy));
                atomicMax(&umax[bi * 3 + 2], fenc(qz));
                atomicMin(&umin[bi * 3 + 0], fenc(qx));
                atomicMin(&umin[bi * 3 + 1], fenc(qy));
                atomicMin(&umin[bi * 3 + 2], fenc(qz));
            }
        }
        __syncwarp();

        float* mdst = outMask + (size_t)base * 30;
        #pragma unroll
        for (int r = 0; r < 15; r++) {
            int j = r * 32 + l;
            mdst[j] = wbuf[j] * sinv[(j * 2185) >> 16];   // j/30 exact for j<480
        }

        // ================= layer 1 -> A fragments (hi/lo bf16 split) =======
        const int p0 = base + lr;
        const int p1 = p0 + 8;
        float x0 = pc1[p0 * 3 + 0], y0 = pc1[p0 * 3 + 1], z0 = pc1[p0 * 3 + 2];
        float x1 = pc1[p1 * 3 + 0], y1 = pc1[p1 * 3 + 1], z1 = pc1[p1 * 3 + 2];

        uint ahi[8][4], alo[8][4];
        #pragma unroll
        for (int kk = 0; kk < 8; kk++) {
            int ib = kk * 16 + lq * 2;
            float4 wv0 = W14[ib],     wv1 = W14[ib + 1];
            float4 wv8 = W14[ib + 8], wv9 = W14[ib + 9];
            float v00 = fmaxf(fmaf(x0, wv0.x, fmaf(y0, wv0.y, fmaf(z0, wv0.z, wv0.w))), 0.f);
            float v01 = fmaxf(fmaf(x0, wv1.x, fmaf(y0, wv1.y, fmaf(z0, wv1.z, wv1.w))), 0.f);
            float v02 = fmaxf(fmaf(x0, wv8.x, fmaf(y0, wv8.y, fmaf(z0, wv8.z, wv8.w))), 0.f);
            float v03 = fmaxf(fmaf(x0, wv9.x, fmaf(y0, wv9.y, fmaf(z0, wv9.z, wv9.w))), 0.f);
            float v10 = fmaxf(fmaf(x1, wv0.x, fmaf(y1, wv0.y, fmaf(z1, wv0.z, wv0.w))), 0.f);
            float v11 = fmaxf(fmaf(x1, wv1.x, fmaf(y1, wv1.y, fmaf(z1, wv1.z, wv1.w))), 0.f);
            float v12 = fmaxf(fmaf(x1, wv8.x, fmaf(y1, wv8.y, fmaf(z1, wv8.z, wv8.w))), 0.f);
            float v13 = fmaxf(fmaf(x1, wv9.x, fmaf(y1, wv9.y, fmaf(z1, wv9.z, wv9.w))), 0.f);

            float h00 = bf16_round(v00), h01 = bf16_round(v01);
            float h02 = bf16_round(v02), h03 = bf16_round(v03);
            float h10 = bf16_round(v10), h11 = bf16_round(v11);
            float h12 = bf16_round(v12), h13 = bf16_round(v13);
            ahi[kk][0] = pack_bf16x2(h00, h01);
            ahi[kk][1] = pack_bf16x2(h10, h11);
            ahi[kk][2] = pack_bf16x2(h02, h03);
            ahi[kk][3] = pack_bf16x2(h12, h13);
            alo[kk][0] = pack_bf16x2(v00 - h00, v01 - h01);
            alo[kk][1] = pack_bf16x2(v10 - h10, v11 - h11);
            alo[kk][2] = pack_bf16x2(v02 - h02, v03 - h03);
            alo[kk][3] = pack_bf16x2(v12 - h12, v13 - h13);
        }

        // ================= GEMM (3-term split) + fused epilogue ============
        float oA0 = 0.f, oA1 = 0.f, oA2 = 0.f, oA3 = 0.f;   // point p0
        float oB0 = 0.f, oB1 = 0.f, oB2 = 0.f, oB3 = 0.f;   // point p1
        for (int n = 0; n < 16; n++) {
            float d00=0.f,d01=0.f,d02=0.f,d03=0.f;   // Ahi*Bhi
            float d10=0.f,d11=0.f,d12=0.f,d13=0.f;   // Ahi*Blo
            float d20=0.f,d21=0.f,d22=0.f,d23=0.f;   // Alo*Bhi
            uint a = bbase + (uint)n * 16u;
            #pragma unroll
            for (int kk = 0; kk < 8; kk++) {
                uint bh0, bh1, bl0, bl1;
                ldsm_x4_t(bh0, bh1, bl0, bl1, a + (uint)kk * (16u * LDB * 2));
                mma16816(d00,d01,d02,d03,
                         ahi[kk][0],ahi[kk][1],ahi[kk][2],ahi[kk][3], bh0,bh1);
                mma16816(d10,d11,d12,d13,
                         ahi[kk][0],ahi[kk][1],ahi[kk][2],ahi[kk][3], bl0,bl1);
                mma16816(d20,d21,d22,d23,
                         alo[kk][0],alo[kk][1],alo[kk][2],alo[kk][3], bh0,bh1);
            }
            int j0 = n * 8 + lq * 2;
            float2 b2p = *(const float2*)&b2s[j0];
            float hA0 = fmaxf(d00 + d10 + d20 + b2p.x, 0.f);
            float hA1 = fmaxf(d01 + d11 + d21 + b2p.y, 0.f);
            float hB0 = fmaxf(d02 + d12 + d22 + b2p.x, 0.f);
            float hB1 = fmaxf(d03 + d13 + d23 + b2p.y, 0.f);
            float4 wA = *(const float4*)&W3s[j0 * 4];
            float4 wB = *(const float4*)&W3s[j0 * 4 + 4];
            oA0 = fmaf(hA0, wA.x, fmaf(hA1, wB.x, oA0));
            oA1 = fmaf(hA0, wA.y, fmaf(hA1, wB.y, oA1));
            oA2 = fmaf(hA0, wA.z, fmaf(hA1, wB.z, oA2));
            oA3 = fmaf(hA0, wA.w, fmaf(hA1, wB.w, oA3));
            oB0 = fmaf(hB0, wA.x, fmaf(hB1, wB.x, oB0));
            oB1 = fmaf(hB0, wA.y, fmaf(hB1, wB.y, oB1));
            oB2 = fmaf(hB0, wA.z, fmaf(hB1, wB.z, oB2));
            oB3 = fmaf(hB0, wA.w, fmaf(hB1, wB.w, oB3));
        }

        // reduce partials across the 4 lanes of each quad
        #pragma unroll
        for (int off = 1; off <= 2; off <<= 1) {
            oA0 += __shfl_xor_sync(0xFFFFFFFFu, oA0, off);
            oA1 += __shfl_xor_sync(0xFFFFFFFFu, oA1, off);
            oA2 += __shfl_xor_sync(0xFFFFFFFFu, oA2, off);
            oA3 += __shfl_xor_sync(0xFFFFFFFFu, oA3, off);
            oB0 += __shfl_xor_sync(0xFFFFFFFFu, oB0, off);
            oB1 += __shfl_xor_sync(0xFFFFFFFFu, oB1, off);
            oB2 += __shfl_xor_sync(0xFFFFFFFFu, oB2, off);
            oB3 += __shfl_xor_sync(0xFFFFFFFFu, oB3, off);
        }
        if (lq == 0) {
            outT[p0 * 3 + 0] = oA0 + b3s[0];
            outT[p0 * 3 + 1] = oA1 + b3s[1];
            outT[p0 * 3 + 2] = oA2 + b3s[2];
            outYaw[p0]       = oA3 + b3s[3];
            outT[p1 * 3 + 0] = oB0 + b3s[0];
            outT[p1 * 3 + 1] = oB1 + b3s[1];
            outT[p1 * 3 + 2] = oB2 + b3s[2];
            outYaw[p1]       = oB3 + b3s[3];
        }
    }

    // block-level segment reduction -> global
    __syncthreads();
    if (tid < KSEG * 3) {
        atomicMax(&g_umax[tid], umax[tid]);
        atomicMin(&g_umin[tid], umin[tid]);
    }
}

// ---------------- kernel: flow ---------------------------------------------
__global__ void k_flow(const float* __restrict__ pc1, float* __restrict__ out)
{
    int idx = blockIdx.x * blockDim.x + threadIdx.x;
    if (idx >= NP) return;

    const float* outT   = out + (size_t)33 * NP;
    const float* outYaw = out + (size_t)36 * NP;

    int ind = g_ind[idx];
    float xcx = g_xc[ind*3+0], xcy = g_xc[ind*3+1], xcz = g_xc[ind*3+2];
    float px = pc1[idx*3+0], py = pc1[idx*3+1], pz = pc1[idx*3+2];
    float dx = px - xcx, dy = py - xcy, dz = pz - xcz;

    float yaw = outYaw[idx];
    float c, s; sincosf(yaw, &s, &c);

    float rx = c*dx - s*dy;
    float ry = s*dx + c*dy;

    float tx = outT[idx*3+0], ty = outT[idx*3+1], tz = outT[idx*3+2];

    out[idx*3+0] = (rx + xcx + tx) - px;
    out[idx*3+1] = (ry + xcy + ty) - py;
    out[idx*3+2] = (dz + xcz + tz) - pz;
}

// ---------------- launcher --------------------------------------------------
extern "C" void kernel_launch(void* const* d_in, const int* in_sizes, int n_in,
                              void* d_out, int out_size)
{
    const float* pc1    = (const float*)d_in[0];
    const float* logits = (const float*)d_in[1];
    const float* W1     = (const float*)d_in[2];
    const float* b1     = (const float*)d_in[3];
    const float* W2     = (const float*)d_in[4];
    const float* b2     = (const float*)d_in[5];
    const float* W3     = (const float*)d_in[6];
    const float* b3     = (const float*)d_in[7];
    float* out = (float*)d_out;

    cudaFuncSetAttribute(k_fused, cudaFuncAttributeMaxDynamicSharedMemorySize,
                         SM_TOTAL);

    k_init<<<1, 128>>>();
    k_fused<<<GRID_MMA, 256, SM_TOTAL>>>(pc1, logits, W1, b1, W2, b2, W3, b3, out);
    k_centers<<<1, 128>>>();
    k_flow<<<(NP + 255) / 256, 256>>>(pc1, out);
}